// round 14
// baseline (speedup 1.0000x reference)
#include <cuda_runtime.h>
#include <cuda_fp16.h>
#include <cstdint>

#define EMAX 262144
#define DD   128
#define DAA  64

// ---------------------------------------------------------------------------
// Device scratch (no allocations allowed)
// ---------------------------------------------------------------------------
__device__ __align__(256) unsigned char g_pm [(size_t)EMAX * DD * 4];   // m_input fp16
__device__ __align__(256) unsigned char g_pxd[(size_t)EMAX * DAA * 4];  // xdown fp16
__device__ __align__(256) unsigned char g_h  [(size_t)8 * EMAX * 8 * 2];// h = sbf@W1 fp16
__device__ float g_agg[(size_t)EMAX * DAA];
__device__ float g_wrbf[6 * DD];
__device__ __align__(256) unsigned char g_wplanes[1 << 20];             // fp16 weight planes

// Weight plane layout (single fp16 plane, B^T rows, STR = NI*2+16)
#define PP       34816                 // 128x128 plane bytes (128*272)
#define OFF_DOWN (9 * PP)              // W_down: 64*272  = 17408
#define OFF_UP   (OFF_DOWN + 17408)    // W_up:   128*144 = 18432

// smem layout for mega kernels
#define SOFF_GATE 0
#define SOFF_W0   3072
#define SOFF_W1   (SOFF_W0 + PP)       // 37888
#define SOFF_X    (SOFF_W1 + PP)       // 72704
#define SOFF_T    (SOFF_X + 34816)     // 107520
#define SMEM_MEGA (SOFF_T + 34816)     // 142336

// ---------------------------------------------------------------------------
// PTX helpers
// ---------------------------------------------------------------------------
__device__ __forceinline__ uint32_t smem_u32(const void* p) {
    uint32_t a;
    asm("{ .reg .u64 t; cvta.to.shared.u64 t, %1; cvt.u32.u64 %0, t; }"
        : "=r"(a) : "l"(p));
    return a;
}
__device__ __forceinline__ void cp_async16(uint32_t dst, const void* src) {
    asm volatile("cp.async.cg.shared.global [%0], [%1], 16;" :: "r"(dst), "l"(src));
}
__device__ __forceinline__ void cp_commit() { asm volatile("cp.async.commit_group;"); }
__device__ __forceinline__ void cp_wait0()  { asm volatile("cp.async.wait_group 0;"); }

__device__ __forceinline__ void ldsm_x4(uint32_t& r0, uint32_t& r1,
                                        uint32_t& r2, uint32_t& r3, uint32_t addr) {
    asm volatile("ldmatrix.sync.aligned.m8n8.x4.shared.b16 {%0,%1,%2,%3}, [%4];"
                 : "=r"(r0), "=r"(r1), "=r"(r2), "=r"(r3) : "r"(addr));
}
__device__ __forceinline__ void mma_f16(float* c, const uint32_t* a,
                                        uint32_t b0, uint32_t b1) {
    asm volatile(
        "mma.sync.aligned.m16n8k16.row.col.f32.f16.f16.f32 "
        "{%0,%1,%2,%3}, {%4,%5,%6,%7}, {%8,%9}, {%0,%1,%2,%3};"
        : "+f"(c[0]), "+f"(c[1]), "+f"(c[2]), "+f"(c[3])
        : "r"(a[0]), "r"(a[1]), "r"(a[2]), "r"(a[3]), "r"(b0), "r"(b1));
}
__device__ __forceinline__ float swishf(float x) {
    return x * (1.0f / (1.0f + __expf(-x)));
}
__device__ __forceinline__ void red_add_v4(float* p, float4 v) {
    asm volatile("red.global.add.v4.f32 [%0], {%1, %2, %3, %4};"
                 :: "l"(p), "f"(v.x), "f"(v.y), "f"(v.z), "f"(v.w) : "memory");
}

// ---------------------------------------------------------------------------
// prep_all: all preprocessing in one kernel (grid.y jobs)
// ---------------------------------------------------------------------------
struct WJob { const float* w; int ni, no, off; };
struct WJobs { WJob j[11]; };

__global__ void prep_all(WJobs jobs,
                         const float* __restrict__ W1, const float* __restrict__ W2,
                         float* __restrict__ wrbf,
                         float* __restrict__ agg, int nAgg4,
                         const float* __restrict__ m_input, __half* __restrict__ pm,
                         int nM8) {
    const int tid = threadIdx.x;
    const int y = blockIdx.y;
    if (y < 11) {
        WJob jb = jobs.j[y];
        const int STRb = jb.ni * 2 + 16;
        const int tot = jb.ni * jb.no;
        for (int i = blockIdx.x * 256 + tid; i < tot; i += gridDim.x * 256) {
            int k = i / jb.no, n = i % jb.no;
            *(__half*)(g_wplanes + jb.off + n * STRb + k * 2) =
                __float2half_rn(jb.w[i]);
        }
    } else if (y == 11) {
        float4 z = make_float4(0.f, 0.f, 0.f, 0.f);
        for (int i = blockIdx.x * 256 + tid; i < nAgg4; i += gridDim.x * 256)
            *(float4*)&agg[(size_t)i * 4] = z;
    } else if (y == 12) {
        if (blockIdx.x == 0 && tid < 128) {
            int c = tid;
            #pragma unroll
            for (int r = 0; r < 6; r++) {
                float s = 0.f;
                #pragma unroll
                for (int j = 0; j < 8; j++) s += W1[r * 8 + j] * W2[j * DD + c];
                wrbf[r * DD + c] = s;
            }
        }
    } else {
        for (int i = blockIdx.x * 256 + tid; i < nM8; i += gridDim.x * 256) {
            const float4* p = (const float4*)&m_input[(size_t)i * 8];
            float4 a = p[0], b = p[1];
            __half2 h[4];
            h[0] = __halves2half2(__float2half_rn(a.x), __float2half_rn(a.y));
            h[1] = __halves2half2(__float2half_rn(a.z), __float2half_rn(a.w));
            h[2] = __halves2half2(__float2half_rn(b.x), __float2half_rn(b.y));
            h[3] = __halves2half2(__float2half_rn(b.z), __float2half_rn(b.w));
            *(uint4*)&pm[(size_t)i * 8] = *(uint4*)h;
        }
    }
}

// ---------------------------------------------------------------------------
// sbf_proj: h[t] = sbf[t] @ W_sbf1   (42 -> 8), fp16 out. Pure stream.
// ---------------------------------------------------------------------------
#define SP_TRIP 128
__global__ __launch_bounds__(256)
void sbf_proj(const float* __restrict__ sbf, const float* __restrict__ W1,
              __half* __restrict__ hout, int Ttot) {
    __shared__ float s_sbf[SP_TRIP * 42];
    __shared__ float s_w1[42 * 8];
    const uint32_t sbs = smem_u32(s_sbf);
    const int tid = threadIdx.x;
    const int base = blockIdx.x * SP_TRIP;
    const int n_t = min(SP_TRIP, Ttot - base);

    for (int i = tid; i < 336; i += 256) s_w1[i] = W1[i];
    if (n_t == SP_TRIP) {
        const char* src = (const char*)(sbf + (size_t)base * 42);
        #pragma unroll 2
        for (int i = tid; i < SP_TRIP * 42 * 4 / 16; i += 256)
            cp_async16(sbs + i * 16, src + i * 16);
        cp_commit(); cp_wait0();
    } else {
        for (int i = tid; i < n_t * 42; i += 256) s_sbf[i] = sbf[(size_t)base * 42 + i];
    }
    __syncthreads();

    const int i = tid >> 1, j0 = (tid & 1) * 4;
    if (i < n_t) {
        float hv[4] = {0.f, 0.f, 0.f, 0.f};
        const float* row = &s_sbf[i * 42];
        #pragma unroll
        for (int k = 0; k < 42; k++) {
            float sv = row[k];
            #pragma unroll
            for (int j = 0; j < 4; j++) hv[j] += sv * s_w1[k * 8 + j0 + j];
        }
        __half2 o[2];
        o[0] = __halves2half2(__float2half_rn(hv[0]), __float2half_rn(hv[1]));
        o[1] = __halves2half2(__float2half_rn(hv[2]), __float2half_rn(hv[3]));
        *(uint2*)&hout[(size_t)(base + i) * 8 + j0] = *(uint2*)o;
    }
}

// ---------------------------------------------------------------------------
// Mega-kernel building blocks (1024 threads, 32 warps)
// ---------------------------------------------------------------------------
template <int NI>
__device__ __forceinline__ void load_act(uint32_t sb, uint32_t offA,
                                         const __half* __restrict__ src,
                                         int row0, int nrows, int tid) {
    constexpr int STR = NI * 2 + 16, NCH = NI / 8, TOT = 128 * NCH;
    #pragma unroll 2
    for (int i = tid; i < TOT; i += 1024) {
        int r = i / NCH, ch = i % NCH;
        int rr = row0 + r; if (rr >= nrows) rr = nrows - 1;
        cp_async16(sb + offA + r * STR + ch * 16, src + (size_t)rr * NI + ch * 8);
    }
}

__device__ __forceinline__ void load_w(uint32_t sb, uint32_t offW,
                                       const unsigned char* __restrict__ src,
                                       int bytes, int tid) {
    #pragma unroll 4
    for (int i = tid * 16; i < bytes; i += 1024 * 16)
        cp_async16(sb + offW + i, src + i);
}

// Single-pass fp16 MMA: acc = A @ W  (both plain fp16)
template <int NI, int NO>
__device__ __forceinline__ void mma1(uint32_t sb, uint32_t offA, uint32_t offW,
                                     int w, int lane, float acc[NO / 32][4]) {
    constexpr int STR = NI * 2 + 16;
    constexpr int WN = NO / 4, NJ = WN / 8, NG = WN / 16;
    const int wm0 = (w & 7) * 16, wn0 = (w >> 3) * WN;
    const int lr = lane & 15, lk = (lane >> 4) * 8;
    #pragma unroll
    for (int nj = 0; nj < NJ; nj++)
        #pragma unroll
        for (int q = 0; q < 4; q++) acc[nj][q] = 0.f;
    #pragma unroll
    for (int k0 = 0; k0 < NI; k0 += 16) {
        uint32_t a4[4];
        ldsm_x4(a4[0], a4[1], a4[2], a4[3],
                sb + offA + (uint32_t)((wm0 + lr) * STR + (k0 + lk) * 2));
        uint32_t bh[NG][4];
        #pragma unroll
        for (int g = 0; g < NG; g++)
            ldsm_x4(bh[g][0], bh[g][1], bh[g][2], bh[g][3],
                    sb + offW + (uint32_t)((wn0 + g * 16 + lr) * STR + (k0 + lk) * 2));
        #pragma unroll
        for (int nj = 0; nj < NJ; nj++)
            mma_f16(acc[nj], a4, bh[nj >> 1][nj & 1], bh[nj >> 1][(nj & 1) + 2]);
    }
}

// Epilogue: bias -> swish -> [gate] -> [residual] -> out.
template <int NO, bool BIAS, bool GATE, int RES, int OUT>
__device__ __forceinline__ void stage_ep2(char* smem, uint32_t offRes, uint32_t offOut,
                                          const float* __restrict__ bias,
                                          const float* __restrict__ rbf,
                                          int row0, int nrows,
                                          __half* __restrict__ yh,
                                          float* __restrict__ yf,
                                          const float* __restrict__ resf,
                                          int w, int lane, float acc[NO / 32][4]) {
    constexpr int NJ = NO / 32, WN = NO / 4;
    const int wm0 = (w & 7) * 16, wn0 = (w >> 3) * WN;
    const int sr = lane >> 2, sc = (lane & 3) * 2;
    #pragma unroll
    for (int hf = 0; hf < 2; hf++) {
        const int r = wm0 + sr + hf * 8;
        const int row = row0 + r;
        const int rc = (row < nrows) ? row : nrows - 1;
        float g6[6];
        if (GATE) {
            #pragma unroll
            for (int j = 0; j < 6; j++) g6[j] = rbf[(size_t)rc * 6 + j];
        }
        #pragma unroll
        for (int nj = 0; nj < NJ; nj++) {
            const int c = wn0 + nj * 8 + sc;
            float v0 = acc[nj][hf * 2], v1 = acc[nj][hf * 2 + 1];
            if (BIAS) { v0 += bias[c]; v1 += bias[c + 1]; }
            v0 = swishf(v0); v1 = swishf(v1);
            if (GATE) {
                float gg0 = 0.f, gg1 = 0.f;
                #pragma unroll
                for (int j = 0; j < 6; j++) {
                    gg0 += g6[j] * ((float*)smem)[j * 128 + c];
                    gg1 += g6[j] * ((float*)smem)[j * 128 + c + 1];
                }
                v0 *= gg0; v1 *= gg1;
            }
            if (RES == 1) {
                float2 f = __half22float2(*(__half2*)(smem + offRes + r * 272 + c * 2));
                v0 += f.x; v1 += f.y;
            } else if (RES == 2) {
                float2 rv = *(const float2*)&resf[(size_t)rc * NO + c];
                v0 += rv.x; v1 += rv.y;
            }
            if (OUT == 2) {
                if (row < nrows)
                    *(float2*)&yf[(size_t)row * NO + c] = make_float2(v0, v1);
            } else {
                __half2 hv = __halves2half2(__float2half_rn(v0), __float2half_rn(v1));
                if (OUT == 0)
                    *(__half2*)(smem + offOut + r * 272 + c * 2) = hv;
                else if (row < nrows)
                    *(__half2*)&yh[(size_t)row * NO + c] = hv;
            }
        }
    }
}

// ---------------------------------------------------------------------------
// mega_kj: x = swish(m@W_kj+b)*gate ; xdown = swish(x@W_down)
// ---------------------------------------------------------------------------
__global__ __launch_bounds__(1024, 1)
void mega_kj(const __half* __restrict__ pm,
             const unsigned char* __restrict__ wp,
             const float* __restrict__ b_kj, const float* __restrict__ rbf,
             const float* __restrict__ wrbf,
             __half* __restrict__ xd, int nrows) {
    extern __shared__ char smem[];
    const uint32_t sb = smem_u32(smem);
    const int tid = threadIdx.x, w = tid >> 5, lane = tid & 31;

    load_w(sb, SOFF_W0, wp + 0, PP, tid);
    load_w(sb, SOFF_W1, wp + OFF_DOWN, 17408, tid);
    cp_commit();
    for (int i = tid; i < 6 * 128; i += 1024) ((float*)smem)[i] = wrbf[i];

    float acc[4][4];
    float acc2[2][4];
    const int ntiles = (nrows + 127) >> 7;
    for (int tile = blockIdx.x; tile < ntiles; tile += gridDim.x) {
        const int row0 = tile << 7;
        load_act<128>(sb, SOFF_X, pm, row0, nrows, tid); cp_commit();
        cp_wait0(); __syncthreads();

        mma1<128, 128>(sb, SOFF_X, SOFF_W0, w, lane, acc);
        stage_ep2<128, true, true, 0, 0>(smem, 0, SOFF_T, b_kj, rbf, row0, nrows,
                                         nullptr, nullptr, nullptr, w, lane, acc);
        __syncthreads();

        mma1<128, 64>(sb, SOFF_T, SOFF_W1, w, lane, acc2);
        stage_ep2<64, false, false, 0, 1>(smem, 0, 0, nullptr, nullptr, row0, nrows,
                                          xd, nullptr, nullptr, w, lane, acc2);
    }
}

// ---------------------------------------------------------------------------
// triplet3: 16 threads per triplet, W_sbf2 slice in registers.
// ---------------------------------------------------------------------------
__global__ __launch_bounds__(256)
void triplet3(const int* __restrict__ expand, const int* __restrict__ reduce,
              const float* __restrict__ Wsbf2,
              const __half* __restrict__ hin, const __half* __restrict__ xh,
              float* __restrict__ agg, int Ttot) {
    const int tid  = threadIdx.x;
    const int lane = tid & 31;
    const int sub  = lane >> 4;
    const int ch   = (lane & 15) * 4;

    float4 w2r[8];
    #pragma unroll
    for (int j = 0; j < 8; j++) w2r[j] = *(const float4*)&Wsbf2[j * 64 + ch];

    const int t = blockIdx.x * 16 + (tid >> 5) * 2 + sub;
    if (t >= Ttot) return;

    uint4 hv4 = *(const uint4*)&hin[(size_t)t * 8];
    float h[8];
    {
        const __half2* hp = (const __half2*)&hv4;
        #pragma unroll
        for (int j = 0; j < 4; j++) {
            float2 f = __half22float2(hp[j]);
            h[2 * j] = f.x; h[2 * j + 1] = f.y;
        }
    }
    const int ekj = expand[t];
    const int eji = reduce[t];

    uint2 xv = *(const uint2*)&xh[(size_t)ekj * DAA + ch];
    float2 xa = __half22float2(((const __half2*)&xv)[0]);
    float2 xb = __half22float2(((const __half2*)&xv)[1]);

    float g0 = 0.f, g1 = 0.f, g2 = 0.f, g3 = 0.f;
    #pragma unroll
    for (int j = 0; j < 8; j++) {
        float hj = h[j];
        g0 += hj * w2r[j].x; g1 += hj * w2r[j].y;
        g2 += hj * w2r[j].z; g3 += hj * w2r[j].w;
    }

    red_add_v4(&agg[(size_t)eji * DAA + ch],
               make_float4(xa.x * g0, xa.y * g1, xb.x * g2, xb.y * g3));
}

// ---------------------------------------------------------------------------
// mega_chain: fused 9-GEMM chain; S1 reads agg fp32 directly.
// ---------------------------------------------------------------------------
__global__ __launch_bounds__(1024, 1)
void mega_chain(const float* __restrict__ aggf, const __half* __restrict__ pm,
                const unsigned char* __restrict__ wp,
                const float* __restrict__ b_ji, const float* __restrict__ b_res_b,
                const float* __restrict__ b_final, const float* __restrict__ b_res_a,
                const float* __restrict__ m_input, float* __restrict__ out,
                int nrows) {
    extern __shared__ char smem[];
    const uint32_t sb = smem_u32(smem);
    const int tid = threadIdx.x, w = tid >> 5, lane = tid & 31;
    float acc[4][4];

    uint32_t wA = SOFF_W0, wB = SOFF_W1;
    load_w(sb, wA, wp + OFF_UP, 18432, tid); cp_commit();

    const int ntiles = (nrows + 127) >> 7;
    for (int tile = blockIdx.x; tile < ntiles; tile += gridDim.x) {
        const int row0 = tile << 7;

        // agg fp32 -> fp16 smem X (STR=144)
        {
            int r = tid >> 3, c0 = (tid & 7) * 8;
            int rr = row0 + r; if (rr >= nrows) rr = nrows - 1;
            float4 a = *(const float4*)&aggf[(size_t)rr * DAA + c0];
            float4 b = *(const float4*)&aggf[(size_t)rr * DAA + c0 + 4];
            __half2 hh[4];
            hh[0] = __halves2half2(__float2half_rn(a.x), __float2half_rn(a.y));
            hh[1] = __halves2half2(__float2half_rn(a.z), __float2half_rn(a.w));
            hh[2] = __halves2half2(__float2half_rn(b.x), __float2half_rn(b.y));
            hh[3] = __halves2half2(__float2half_rn(b.z), __float2half_rn(b.w));
            *(uint4*)(smem + SOFF_X + r * 144 + c0 * 2) = *(uint4*)hh;
        }
        cp_wait0(); __syncthreads();

        // S1: p = swish(agg @ W_up)
        mma1<64, 128>(sb, SOFF_X, wA, w, lane, acc);
        __syncthreads();
        load_act<128>(sb, SOFF_X, pm, row0, nrows, tid);
        load_w(sb, wB, wp + 1 * PP, PP, tid); cp_commit();
        stage_ep2<128, false, false, 0, 0>(smem, 0, SOFF_T, nullptr, nullptr, row0, nrows,
                                           nullptr, nullptr, nullptr, w, lane, acc);
        cp_wait0(); __syncthreads(); { uint32_t t = wA; wA = wB; wB = t; }

        // S2: m1 = swish(m@W_ji+b) + p
        mma1<128, 128>(sb, SOFF_X, wA, w, lane, acc);
        load_w(sb, wB, wp + 2 * PP, PP, tid); cp_commit();
        stage_ep2<128, true, false, 1, 0>(smem, SOFF_T, SOFF_T, b_ji, nullptr, row0, nrows,
                                          nullptr, nullptr, nullptr, w, lane, acc);
        cp_wait0(); __syncthreads(); { uint32_t t = wA; wA = wB; wB = t; }

        // S3: t = swish(m1@Wb0+b)
        mma1<128, 128>(sb, SOFF_T, wA, w, lane, acc);
        load_w(sb, wB, wp + 3 * PP, PP, tid); cp_commit();
        stage_ep2<128, true, false, 0, 0>(smem, 0, SOFF_X, b_res_b, nullptr, row0, nrows,
                                          nullptr, nullptr, nullptr, w, lane, acc);
        cp_wait0(); __syncthreads(); { uint32_t t = wA; wA = wB; wB = t; }

        // S4: m2 = m1 + swish(t@Wb1+b)
        mma1<128, 128>(sb, SOFF_X, wA, w, lane, acc);
        load_w(sb, wB, wp + 4 * PP, PP, tid); cp_commit();
        stage_ep2<128, true, false, 1, 0>(smem, SOFF_T, SOFF_T, b_res_b + DD, nullptr, row0, nrows,
                                          nullptr, nullptr, nullptr, w, lane, acc);
        cp_wait0(); __syncthreads(); { uint32_t t = wA; wA = wB; wB = t; }

        // S5: m3 = swish(m2@W_final+b) + m_input
        mma1<128, 128>(sb, SOFF_T, wA, w, lane, acc);
        load_w(sb, wB, wp + 5 * PP, PP, tid); cp_commit();
        stage_ep2<128, true, false, 2, 0>(smem, 0, SOFF_X, b_final, nullptr, row0, nrows,
                                          nullptr, nullptr, m_input, w, lane, acc);
        cp_wait0(); __syncthreads(); { uint32_t t = wA; wA = wB; wB = t; }

        // S6: t = swish(m3@Wa00+b)
        mma1<128, 128>(sb, SOFF_X, wA, w, lane, acc);
        load_w(sb, wB, wp + 6 * PP, PP, tid); cp_commit();
        stage_ep2<128, true, false, 0, 0>(smem, 0, SOFF_T, b_res_a, nullptr, row0, nrows,
                                          nullptr, nullptr, nullptr, w, lane, acc);
        cp_wait0(); __syncthreads(); { uint32_t t = wA; wA = wB; wB = t; }

        // S7: m4 = m3 + swish(t@Wa01+b)
        mma1<128, 128>(sb, SOFF_T, wA, w, lane, acc);
        load_w(sb, wB, wp + 7 * PP, PP, tid); cp_commit();
        stage_ep2<128, true, false, 1, 0>(smem, SOFF_X, SOFF_X, b_res_a + DD, nullptr, row0, nrows,
                                          nullptr, nullptr, nullptr, w, lane, acc);
        cp_wait0(); __syncthreads(); { uint32_t t = wA; wA = wB; wB = t; }

        // S8: t = swish(m4@Wa10+b)
        mma1<128, 128>(sb, SOFF_X, wA, w, lane, acc);
        load_w(sb, wB, wp + 8 * PP, PP, tid); cp_commit();
        stage_ep2<128, true, false, 0, 0>(smem, 0, SOFF_T, b_res_a + 2 * DD, nullptr, row0, nrows,
                                          nullptr, nullptr, nullptr, w, lane, acc);
        cp_wait0(); __syncthreads(); { uint32_t t = wA; wA = wB; wB = t; }

        // S9: out = m4 + swish(t@Wa11+b)  -> gmem fp32
        mma1<128, 128>(sb, SOFF_T, wA, w, lane, acc);
        load_w(sb, wB, wp + OFF_UP, 18432, tid); cp_commit();
        stage_ep2<128, true, false, 1, 2>(smem, SOFF_X, 0, b_res_a + 3 * DD, nullptr, row0, nrows,
                                          nullptr, out, nullptr, w, lane, acc);
        cp_wait0(); __syncthreads(); { uint32_t t = wA; wA = wB; wB = t; }
    }
}

// ---------------------------------------------------------------------------
// Host launcher
// ---------------------------------------------------------------------------
extern "C" void kernel_launch(void* const* d_in, const int* in_sizes, int n_in,
                              void* d_out, int out_size) {
    const float* m_input = (const float*)d_in[0];
    const float* rbf     = (const float*)d_in[1];
    const float* sbf     = (const float*)d_in[2];
    const int*   expand  = (const int*)d_in[3];
    const int*   reduce  = (const int*)d_in[4];
    const float* W_kj    = (const float*)d_in[5];
    const float* b_kj    = (const float*)d_in[6];
    const float* W_rbf1  = (const float*)d_in[7];
    const float* W_rbf2  = (const float*)d_in[8];
    const float* W_sbf1  = (const float*)d_in[9];
    const float* W_sbf2  = (const float*)d_in[10];
    const float* W_down  = (const float*)d_in[11];
    const float* W_up    = (const float*)d_in[12];
    const float* W_ji    = (const float*)d_in[13];
    const float* b_ji    = (const float*)d_in[14];
    const float* W_res_b = (const float*)d_in[15];
    const float* b_res_b = (const float*)d_in[16];
    const float* W_final = (const float*)d_in[17];
    const float* b_final = (const float*)d_in[18];
    const float* W_res_a = (const float*)d_in[19];
    const float* b_res_a = (const float*)d_in[20];
    float* out = (float*)d_out;

    const int E = in_sizes[0] / DD;
    const int T = in_sizes[3];

    unsigned char *pm, *pxd, *ph, *wp;
    float *agg, *wrbf;
    cudaGetSymbolAddress((void**)&pm,  g_pm);
    cudaGetSymbolAddress((void**)&pxd, g_pxd);
    cudaGetSymbolAddress((void**)&ph,  g_h);
    cudaGetSymbolAddress((void**)&agg, g_agg);
    cudaGetSymbolAddress((void**)&wrbf, g_wrbf);
    cudaGetSymbolAddress((void**)&wp,  g_wplanes);

    __half* pm_h  = (__half*)pm;
    __half* pxd_h = (__half*)pxd;
    __half* h_buf = (__half*)ph;

    int smcnt = 148, dev = 0;
    cudaGetDevice(&dev);
    cudaDeviceGetAttribute(&smcnt, cudaDevAttrMultiProcessorCount, dev);
    const int ntiles = (E + 127) / 128;
    const int grid = (ntiles < smcnt) ? ntiles : smcnt;

    cudaFuncSetAttribute(mega_kj,    cudaFuncAttributeMaxDynamicSharedMemorySize, SMEM_MEGA);
    cudaFuncSetAttribute(mega_chain, cudaFuncAttributeMaxDynamicSharedMemorySize, SMEM_MEGA);

    // 1) all preprocessing in one kernel
    {
        WJobs jobs;
        jobs.j[0]  = {W_kj,            128, 128, 0 * PP};
        jobs.j[1]  = {W_ji,            128, 128, 1 * PP};
        jobs.j[2]  = {W_res_b,         128, 128, 2 * PP};
        jobs.j[3]  = {W_res_b + 16384, 128, 128, 3 * PP};
        jobs.j[4]  = {W_final,         128, 128, 4 * PP};
        jobs.j[5]  = {W_res_a,         128, 128, 5 * PP};
        jobs.j[6]  = {W_res_a + 16384, 128, 128, 6 * PP};
        jobs.j[7]  = {W_res_a + 32768, 128, 128, 7 * PP};
        jobs.j[8]  = {W_res_a + 49152, 128, 128, 8 * PP};
        jobs.j[9]  = {W_down,          128, 64,  OFF_DOWN};
        jobs.j[10] = {W_up,            64,  128, OFF_UP};
        dim3 g(256, 14);
        prep_all<<<g, 256>>>(jobs, W_rbf1, W_rbf2, wrbf,
                             agg, E * DAA / 4, m_input, pm_h, E * DD / 8);
    }
    // 2) h = sbf @ W_sbf1 (fp16)
    sbf_proj<<<(T + SP_TRIP - 1) / SP_TRIP, 256>>>(sbf, W_sbf1, h_buf, T);
    // 3) fused kj+gate+down
    mega_kj<<<grid, 1024, SMEM_MEGA>>>(pm_h, wp, b_kj, rbf, wrbf, pxd_h, E);
    // 4) triplet gather/gate/scatter
    triplet3<<<(T + 15) / 16, 256>>>(expand, reduce, W_sbf2, h_buf, pxd_h, agg, T);
    // 5) fused 9-GEMM chain -> out
    mega_chain<<<grid, 1024, SMEM_MEGA>>>(agg, pm_h, wp,
                                          b_ji, b_res_b, b_final, b_res_a,
                                          m_input, out, E);
}